// round 3
// baseline (speedup 1.0000x reference)
#include <cuda_runtime.h>
#include <cstdint>

#define VOCAB   128000
#define NT      1024
#define CH      8000            // floats per chunk (32000 bytes)
#define CH4     (CH / 4)
#define NCH     (VOCAB / CH)    // 16 chunks per row
#define CAP     4608
#define SUBCAP  512
#define NEGV    (-1000000000.0f)
#define FULLMASK 0xffffffffu

// dynamic smem: chunkbuf(2*CH floats) + buf(CAP) + bidx(CAP) + hist(1024)
#define DYN_SMEM ((2 * CH + 2 * CAP + 1024) * 4)

__device__ __forceinline__ uint32_t smem_u32(const void* p) {
    uint32_t a;
    asm("{ .reg .u64 t; cvta.to.shared.u64 t, %1; cvt.u32.u64 %0, t; }" : "=r"(a) : "l"(p));
    return a;
}
__device__ __forceinline__ void mbar_init(uint32_t mbar, uint32_t cnt) {
    asm volatile("mbarrier.init.shared.b64 [%0], %1;" :: "r"(mbar), "r"(cnt) : "memory");
}
__device__ __forceinline__ void mbar_expect_tx(uint32_t mbar, uint32_t bytes) {
    asm volatile("mbarrier.arrive.expect_tx.shared.b64 _, [%0], %1;" :: "r"(mbar), "r"(bytes) : "memory");
}
__device__ __forceinline__ void bulk_g2s(uint32_t dst, const void* src, uint32_t bytes, uint32_t mbar) {
    asm volatile(
        "cp.async.bulk.shared::cluster.global.mbarrier::complete_tx::bytes [%0], [%1], %2, [%3];"
        :: "r"(dst), "l"(src), "r"(bytes), "r"(mbar) : "memory");
}
__device__ __forceinline__ void mbar_wait(uint32_t mbar, uint32_t parity) {
    uint32_t done;
    asm volatile(
        "{\n\t.reg .pred p;\n\t"
        "mbarrier.try_wait.parity.acquire.cta.shared::cta.b64 p, [%1], %2;\n\t"
        "selp.b32 %0, 1, 0, p;\n\t}"
        : "=r"(done) : "r"(mbar), "r"(parity) : "memory");
    if (!done) {
        asm volatile(
            "{\n\t.reg .pred P1;\n\t"
            "W_%=:\n\t"
            "mbarrier.try_wait.parity.acquire.cta.shared::cta.b64 P1, [%0], %1, 0x989680;\n\t"
            "@P1 bra.uni D_%=;\n\t"
            "bra.uni W_%=;\n\t"
            "D_%=:\n\t}"
            :: "r"(mbar), "r"(parity) : "memory");
    }
}

__global__ __launch_bounds__(NT, 2)
void topk_topp_tma(const float* __restrict__ in, float* __restrict__ out) {
    extern __shared__ __align__(128) float dynsm[];
    float* chunkbuf = dynsm;                         // 2 * CH floats
    float* buf      = dynsm + 2 * CH;                // CAP values
    int*   bidx     = (int*)(dynsm + 2 * CH + CAP);  // CAP indices
    int*   hist     = (int*)(dynsm + 2 * CH + 2 * CAP); // 1024 bins

    __shared__ __align__(8) unsigned long long mbar_s[2];
    __shared__ float warp2nd[32];
    __shared__ float warpmax[32];
    __shared__ float topbuf[SUBCAP];
    __shared__ float topsorted[50];
    __shared__ float e50[50];
    __shared__ int   s_cnt, s_scnt, s_b1;
    __shared__ float s_t0, s_M, s_thresh;

    const int tid  = threadIdx.x;
    const int lane = tid & 31;
    const int wid  = tid >> 5;
    const float* __restrict__ x = in  + (size_t)blockIdx.x * VOCAB;
    float* __restrict__ y       = out + (size_t)blockIdx.x * VOCAB;

    const uint32_t mb0 = smem_u32(&mbar_s[0]);
    const uint32_t mb1 = smem_u32(&mbar_s[1]);
    const uint32_t sbase = smem_u32(chunkbuf);

    // ---------- Phase 0: init + kick off first 2 TMA chunks ----------
    hist[tid] = 0;
    if (tid == 0) {
        s_cnt = 0; s_scnt = 0; s_b1 = 0;
        mbar_init(mb0, 1);
        mbar_init(mb1, 1);
    }
    if (tid < 50) topsorted[tid] = NEGV;
    __syncthreads();
    if (tid == 0) {
        mbar_expect_tx(mb0, CH * 4);
        bulk_g2s(sbase, x, CH * 4, mb0);
        mbar_expect_tx(mb1, CH * 4);
        bulk_g2s(sbase + CH * 4, x + CH, CH * 4, mb1);
    }

    // ---------- Phase 1: sample 8192 elems (overlaps TMA), per-warp top-2 ----------
    const float4* __restrict__ xs = (const float4*)(x + wid * 4000);
    float4 sa = xs[lane * 2];
    float4 sb = xs[lane * 2 + 1];
    float sv[8] = {sa.x, sa.y, sa.z, sa.w, sb.x, sb.y, sb.z, sb.w};

    float lm = sv[0];
#pragma unroll
    for (int k = 1; k < 8; k++) lm = fmaxf(lm, sv[k]);
    float wm = lm;
#pragma unroll
    for (int off = 16; off > 0; off >>= 1)
        wm = fmaxf(wm, __shfl_xor_sync(FULLMASK, wm, off));
    unsigned bal = __ballot_sync(FULLMASK, lm == wm);
    if (lane == (__ffs(bal) - 1)) {
        bool done = false;
#pragma unroll
        for (int k = 0; k < 8; k++)
            if (!done && sv[k] == wm) { sv[k] = -3.4e38f; done = true; }
    }
    float lm2 = sv[0];
#pragma unroll
    for (int k = 1; k < 8; k++) lm2 = fmaxf(lm2, sv[k]);
    float wm2 = lm2;
#pragma unroll
    for (int off = 16; off > 0; off >>= 1)
        wm2 = fmaxf(wm2, __shfl_xor_sync(FULLMASK, wm2, off));
    if (lane == 0) { warpmax[wid] = wm; warp2nd[wid] = wm2; }
    __syncthreads();

    if (tid == 0) {
        // t0 = 7th-smallest warp-2nd-max: 26 warps contribute >=2 samples >= t0
        // -> >=52 row elements >= t0 -> t0 <= row's 50th largest.
        float a[32];
        float M = warpmax[0];
        for (int w = 0; w < 32; w++) { a[w] = warp2nd[w]; M = fmaxf(M, warpmax[w]); }
        for (int k = 0; k < 7; k++) {
            int mi = k;
            for (int j = k + 1; j < 32; j++) if (a[j] < a[mi]) mi = j;
            float t = a[k]; a[k] = a[mi]; a[mi] = t;
        }
        s_t0 = a[6];
        s_M  = M;
    }
    __syncthreads();
    const float t0 = s_t0;
    const float M  = s_M;
    const float scale = (M > t0) ? (1023.0f / (M - t0)) : 0.0f;

    // ---------- Phase 2: pipelined chunk processing ----------
    // chunk c lands in buffer c&1, mbar c&1, parity (c>>1)&1.
    for (int c = 0; c < NCH; c++) {
        const uint32_t mb = (c & 1) ? mb1 : mb0;
        mbar_wait(mb, (c >> 1) & 1);

        const float4* __restrict__ b4 = (const float4*)(chunkbuf + (c & 1) * CH);
        float4* __restrict__ y4 = (float4*)(y + c * CH);
        const int base = c * CH;
        for (int i = tid; i < CH4; i += NT) {
            float4 v = b4[i];
            float4 w;
            w.x = (v.x >= t0) ? v.x : NEGV;
            w.y = (v.y >= t0) ? v.y : NEGV;
            w.z = (v.z >= t0) ? v.z : NEGV;
            w.w = (v.w >= t0) ? v.w : NEGV;
            __stcs(&y4[i], w);
            if (v.x >= t0) { int p = atomicAdd(&s_cnt, 1); if (p < CAP) { buf[p] = v.x; bidx[p] = base + 4*i;     int b = (int)((v.x - t0) * scale); b = b > 1023 ? 1023 : (b < 0 ? 0 : b); atomicAdd(&hist[b], 1);} }
            if (v.y >= t0) { int p = atomicAdd(&s_cnt, 1); if (p < CAP) { buf[p] = v.y; bidx[p] = base + 4*i + 1; int b = (int)((v.y - t0) * scale); b = b > 1023 ? 1023 : (b < 0 ? 0 : b); atomicAdd(&hist[b], 1);} }
            if (v.z >= t0) { int p = atomicAdd(&s_cnt, 1); if (p < CAP) { buf[p] = v.z; bidx[p] = base + 4*i + 2; int b = (int)((v.z - t0) * scale); b = b > 1023 ? 1023 : (b < 0 ? 0 : b); atomicAdd(&hist[b], 1);} }
            if (v.w >= t0) { int p = atomicAdd(&s_cnt, 1); if (p < CAP) { buf[p] = v.w; bidx[p] = base + 4*i + 3; int b = (int)((v.w - t0) * scale); b = b > 1023 ? 1023 : (b < 0 ? 0 : b); atomicAdd(&hist[b], 1);} }
        }
        __syncthreads();   // all threads done reading buffer c&1
        if (tid == 0 && c + 2 < NCH) {
            mbar_expect_tx(mb, CH * 4);
            bulk_g2s(sbase + (c & 1) * CH * 4, x + (c + 2) * CH, CH * 4, mb);
        }
    }
    __syncthreads();
    int cnt = s_cnt; if (cnt > CAP) cnt = CAP;

    // ---------- Phase 4: B1 = largest bin with suffix count >= 50 (warp 0) ----------
    if (wid == 0) {
        int c = 0;
        for (int j = 0; j < 32; j++) c += hist[lane * 32 + j];
        int s = c;
#pragma unroll
        for (int off = 1; off < 32; off <<= 1) {
            int t = __shfl_down_sync(FULLMASK, s, off);
            if (lane + off < 32) s += t;
        }
        unsigned bb = __ballot_sync(FULLMASK, (s >= 50) && (s - c < 50));
        if (bb) {
            int L = __ffs(bb) - 1;
            if (lane == L) {
                int acc = s - c;
                int B1 = L * 32;
                for (int j = 31; j >= 0; j--) {
                    acc += hist[L * 32 + j];
                    if (acc >= 50) { B1 = L * 32 + j; break; }
                }
                s_b1 = B1;
            }
        }
    }
    __syncthreads();
    const int B1 = s_b1;

    // ---------- Phase 5: sub-candidates (bin >= B1) ----------
    for (int i = tid; i < cnt; i += NT) {
        float v = buf[i];
        int b = (int)((v - t0) * scale);
        b = b < 0 ? 0 : (b > 1023 ? 1023 : b);
        if (b >= B1) { int p = atomicAdd(&s_scnt, 1); if (p < SUBCAP) topbuf[p] = v; }
    }
    __syncthreads();
    int sn = s_scnt; if (sn > SUBCAP) sn = SUBCAP;

    // ---------- Phase 6: rank-sort, keep top 50 descending ----------
    for (int i = tid; i < sn; i += NT) {
        float vi = topbuf[i];
        int r = 0;
        for (int j = 0; j < sn; j++) {
            float vj = topbuf[j];
            r += (vj > vi) || (vj == vi && j < i);
        }
        if (r < 50) topsorted[r] = vi;
    }
    __syncthreads();

    // ---------- Phase 7: softmax over top-50 (parallel exp) + nucleus cutoff ----------
    if (tid < 50) e50[tid] = expf(topsorted[tid] - topsorted[0]);
    __syncthreads();
    if (tid == 0) {
        float S = 0.0f;
        for (int i = 0; i < 50; i++) S += e50[i];
        float inv = 1.0f / S;
        float cum = e50[0] * inv;
        int m = 1;
        for (int i = 1; i < 50; i++) {
            if (cum <= 0.9f) m++;
            cum += e50[i] * inv;
        }
        s_thresh = topsorted[m - 1];
    }
    __syncthreads();

    // ---------- Phase 8: scatter fixup of failed candidates ----------
    const float t = s_thresh;
    for (int i = tid; i < cnt; i += NT)
        if (buf[i] < t) y[bidx[i]] = NEGV;
}

extern "C" void kernel_launch(void* const* d_in, const int* in_sizes, int n_in,
                              void* d_out, int out_size) {
    const float* logits = (const float*)d_in[0];
    float* out = (float*)d_out;
    const int rows = out_size / VOCAB;  // 256
    cudaFuncSetAttribute(topk_topp_tma,
                         cudaFuncAttributeMaxDynamicSharedMemorySize, DYN_SMEM);
    topk_topp_tma<<<rows, NT, DYN_SMEM>>>(logits, out);
}

// round 4
// speedup vs baseline: 1.1445x; 1.1445x over previous
#include <cuda_runtime.h>

#define VOCAB 128000
#define VOCAB4 (VOCAB / 4)
#define NT 1024
#define CAP 6144
#define SUBCAP 512
#define NEGV (-1000000000.0f)
#define FULLMASK 0xffffffffu

#define DYN_SMEM (CAP * 8 + 1024 * 4)   // buf + bidx + hist = 53248 bytes

__device__ __forceinline__ void filt_store(float4 v, float t0, float4* dst) {
    float4 w;
    w.x = (v.x >= t0) ? v.x : NEGV;
    w.y = (v.y >= t0) ? v.y : NEGV;
    w.z = (v.z >= t0) ? v.z : NEGV;
    w.w = (v.w >= t0) ? v.w : NEGV;
    __stcs(dst, w);
}

__global__ __launch_bounds__(NT, 2)
void topk_topp_fused(const float* __restrict__ in, float* __restrict__ out) {
    extern __shared__ char dyn[];
    float* buf  = (float*)dyn;                  // CAP candidate values
    int*   bidx = (int*)(dyn + CAP * 4);        // CAP candidate indices
    int*   hist = (int*)(dyn + CAP * 8);        // 1024 bins

    __shared__ float warp2nd[32];
    __shared__ float warpmax[32];
    __shared__ float topbuf[SUBCAP];
    __shared__ float topsorted[50];
    __shared__ float e50[50];
    __shared__ int   s_cnt, s_scnt, s_b1;
    __shared__ float s_t0, s_M, s_thresh;

    const int tid  = threadIdx.x;
    const int lane = tid & 31;
    const int wid  = tid >> 5;
    const float* __restrict__ x = in  + (size_t)blockIdx.x * VOCAB;
    float* __restrict__ y       = out + (size_t)blockIdx.x * VOCAB;

    // ---------- Phase 0: init ----------
    hist[tid] = 0;
    if (tid == 0) { s_cnt = 0; s_scnt = 0; s_b1 = 0; }
    if (tid < 50) topsorted[tid] = NEGV;

    // ---------- Phase 1: sample 8192 elems, per-warp top-2 ----------
    const float4* __restrict__ xs = (const float4*)(x + wid * 4000);
    float4 sa = xs[lane * 2];
    float4 sb = xs[lane * 2 + 1];
    float sv[8] = {sa.x, sa.y, sa.z, sa.w, sb.x, sb.y, sb.z, sb.w};

    float lm = sv[0];
#pragma unroll
    for (int k = 1; k < 8; k++) lm = fmaxf(lm, sv[k]);
    float wm = lm;
#pragma unroll
    for (int off = 16; off > 0; off >>= 1)
        wm = fmaxf(wm, __shfl_xor_sync(FULLMASK, wm, off));
    unsigned bal = __ballot_sync(FULLMASK, lm == wm);
    if (lane == (__ffs(bal) - 1)) {
        bool done = false;
#pragma unroll
        for (int k = 0; k < 8; k++)
            if (!done && sv[k] == wm) { sv[k] = -3.4e38f; done = true; }
    }
    float lm2 = sv[0];
#pragma unroll
    for (int k = 1; k < 8; k++) lm2 = fmaxf(lm2, sv[k]);
    float wm2 = lm2;
#pragma unroll
    for (int off = 16; off > 0; off >>= 1)
        wm2 = fmaxf(wm2, __shfl_xor_sync(FULLMASK, wm2, off));
    if (lane == 0) { warpmax[wid] = wm; warp2nd[wid] = wm2; }
    __syncthreads();

    if (tid == 0) {
        // t0 = 7th-smallest warp-2nd-max: 26 warps contribute >= 2 samples >= t0
        // -> >= 52 row elements >= t0 -> t0 <= row's 50th largest
        // -> candidate set provably contains the top-50.
        float a[32];
        float M = warpmax[0];
        for (int w = 0; w < 32; w++) { a[w] = warp2nd[w]; M = fmaxf(M, warpmax[w]); }
        for (int k = 0; k < 7; k++) {
            int mi = k;
            for (int j = k + 1; j < 32; j++) if (a[j] < a[mi]) mi = j;
            float t = a[k]; a[k] = a[mi]; a[mi] = t;
        }
        s_t0 = a[6];
        s_M  = M;
    }
    __syncthreads();
    const float t0 = s_t0;
    const float M  = s_M;

    // ---------- Phase 2: single fused pass, 2-wide loads, warp-aggregated collect ----------
    const float4* __restrict__ x4 = (const float4*)x;
    float4* __restrict__ y4 = (float4*)y;

    for (int i = tid; i < VOCAB4; i += 2 * NT) {
        const int j = i + NT;
        const bool hb = (j < VOCAB4);
        // issue both loads before any processing (MLP = 2 per thread)
        float4 va = x4[i];
        float4 vb;
        if (hb) vb = x4[j]; else { vb.x = NEGV; vb.y = NEGV; vb.z = NEGV; vb.w = NEGV; }

        filt_store(va, t0, &y4[i]);
        if (hb) filt_store(vb, t0, &y4[j]);

        // warp-aggregated candidate collection (all lanes participate in ballots)
        unsigned m0 = __ballot_sync(FULLMASK, va.x >= t0);
        unsigned m1 = __ballot_sync(FULLMASK, va.y >= t0);
        unsigned m2 = __ballot_sync(FULLMASK, va.z >= t0);
        unsigned m3 = __ballot_sync(FULLMASK, va.w >= t0);
        unsigned n0 = __ballot_sync(FULLMASK, vb.x >= t0);
        unsigned n1 = __ballot_sync(FULLMASK, vb.y >= t0);
        unsigned n2 = __ballot_sync(FULLMASK, vb.z >= t0);
        unsigned n3 = __ballot_sync(FULLMASK, vb.w >= t0);
        int total = __popc(m0) + __popc(m1) + __popc(m2) + __popc(m3)
                  + __popc(n0) + __popc(n1) + __popc(n2) + __popc(n3);
        if (total) {
            int base = 0;
            if (lane == 0) base = atomicAdd(&s_cnt, total);
            base = __shfl_sync(FULLMASK, base, 0);
            const unsigned lt = (1u << lane) - 1u;
            int off = base;
            if (va.x >= t0) { int p = off + __popc(m0 & lt); if (p < CAP) { buf[p] = va.x; bidx[p] = 4 * i; } }
            off += __popc(m0);
            if (va.y >= t0) { int p = off + __popc(m1 & lt); if (p < CAP) { buf[p] = va.y; bidx[p] = 4 * i + 1; } }
            off += __popc(m1);
            if (va.z >= t0) { int p = off + __popc(m2 & lt); if (p < CAP) { buf[p] = va.z; bidx[p] = 4 * i + 2; } }
            off += __popc(m2);
            if (va.w >= t0) { int p = off + __popc(m3 & lt); if (p < CAP) { buf[p] = va.w; bidx[p] = 4 * i + 3; } }
            off += __popc(m3);
            if (vb.x >= t0) { int p = off + __popc(n0 & lt); if (p < CAP) { buf[p] = vb.x; bidx[p] = 4 * j; } }
            off += __popc(n0);
            if (vb.y >= t0) { int p = off + __popc(n1 & lt); if (p < CAP) { buf[p] = vb.y; bidx[p] = 4 * j + 1; } }
            off += __popc(n1);
            if (vb.z >= t0) { int p = off + __popc(n2 & lt); if (p < CAP) { buf[p] = vb.z; bidx[p] = 4 * j + 2; } }
            off += __popc(n2);
            if (vb.w >= t0) { int p = off + __popc(n3 & lt); if (p < CAP) { buf[p] = vb.w; bidx[p] = 4 * j + 3; } }
        }
    }
    __syncthreads();
    int cnt = s_cnt; if (cnt > CAP) cnt = CAP;

    // ---------- Phase 3: 1024-bin linear histogram over [t0, M] ----------
    const float scale = (M > t0) ? (1023.0f / (M - t0)) : 0.0f;
    for (int i = tid; i < cnt; i += NT) {
        int b = (int)((buf[i] - t0) * scale);
        b = b < 0 ? 0 : (b > 1023 ? 1023 : b);
        atomicAdd(&hist[b], 1);
    }
    __syncthreads();

    // ---------- Phase 4: B1 = largest bin with suffix count >= 50 (warp 0) ----------
    if (wid == 0) {
        int c = 0;
        for (int jj = 0; jj < 32; jj++) c += hist[lane * 32 + jj];
        int s = c;
#pragma unroll
        for (int off = 1; off < 32; off <<= 1) {
            int t = __shfl_down_sync(FULLMASK, s, off);
            if (lane + off < 32) s += t;
        }
        unsigned bb = __ballot_sync(FULLMASK, (s >= 50) && (s - c < 50));
        if (bb) {
            int L = __ffs(bb) - 1;
            if (lane == L) {
                int acc = s - c;
                int B1 = L * 32;
                for (int jj = 31; jj >= 0; jj--) {
                    acc += hist[L * 32 + jj];
                    if (acc >= 50) { B1 = L * 32 + jj; break; }
                }
                s_b1 = B1;
            }
        }
    }
    __syncthreads();
    const int B1 = s_b1;

    // ---------- Phase 5: sub-candidates (bin >= B1) ----------
    for (int i = tid; i < cnt; i += NT) {
        float v = buf[i];
        int b = (int)((v - t0) * scale);
        b = b < 0 ? 0 : (b > 1023 ? 1023 : b);
        if (b >= B1) { int p = atomicAdd(&s_scnt, 1); if (p < SUBCAP) topbuf[p] = v; }
    }
    __syncthreads();
    int sn = s_scnt; if (sn > SUBCAP) sn = SUBCAP;

    // ---------- Phase 6: rank-sort, keep top 50 descending ----------
    for (int i = tid; i < sn; i += NT) {
        float vi = topbuf[i];
        int r = 0;
        for (int jj = 0; jj < sn; jj++) {
            float vj = topbuf[jj];
            r += (vj > vi) || (vj == vi && jj < i);
        }
        if (r < 50) topsorted[r] = vi;
    }
    __syncthreads();

    // ---------- Phase 7: softmax over top-50 (parallel exp) + nucleus cutoff ----------
    if (tid < 50) e50[tid] = expf(topsorted[tid] - topsorted[0]);
    __syncthreads();
    if (tid == 0) {
        float S = 0.0f;
        for (int i = 0; i < 50; i++) S += e50[i];
        float inv = 1.0f / S;
        float cum = e50[0] * inv;
        int m = 1;
        for (int i = 1; i < 50; i++) {
            if (cum <= 0.9f) m++;
            cum += e50[i] * inv;
        }
        s_thresh = topsorted[m - 1];
    }
    __syncthreads();

    // ---------- Phase 8: scatter fixup of failed candidates ----------
    const float t = s_thresh;
    for (int i = tid; i < cnt; i += NT)
        if (buf[i] < t) y[bidx[i]] = NEGV;
}

extern "C" void kernel_launch(void* const* d_in, const int* in_sizes, int n_in,
                              void* d_out, int out_size) {
    const float* logits = (const float*)d_in[0];
    float* out = (float*)d_out;
    const int rows = out_size / VOCAB;  // 256
    cudaFuncSetAttribute(topk_topp_fused,
                         cudaFuncAttributeMaxDynamicSharedMemorySize, DYN_SMEM);
    topk_topp_fused<<<rows, NT, DYN_SMEM>>>(logits, out);
}